// round 7
// baseline (speedup 1.0000x reference)
#include <cuda_runtime.h>

#define B_SZ 32
#define S_LEN 2048
#define D_MODEL 1024
#define NSTATE 256
#define LN_EPS 1e-5f

__device__ float g_u[B_SZ * S_LEN];
__device__ float g_s[B_SZ * S_LEN];

__device__ __forceinline__ float warp_sum(float v) {
    #pragma unroll
    for (int o = 16; o; o >>= 1) v += __shfl_xor_sync(0xffffffffu, v, o);
    return v;
}

// Kernel 1: u[b,s] = mean_k x[b,s,k].  One warp per row of 1024.  (at DRAM roofline)
__global__ void mean_kernel(const float* __restrict__ x) {
    int gwarp = (blockIdx.x * blockDim.x + threadIdx.x) >> 5;
    int lane  = threadIdx.x & 31;
    const float4* xp = (const float4*)(x + (size_t)gwarp * D_MODEL);
    float s = 0.f;
    #pragma unroll
    for (int k = 0; k < 8; k++) {
        float4 v = xp[lane + 32 * k];
        s += (v.x + v.y) + (v.z + v.w);
    }
    s = warp_sum(s);
    if (lane == 0) g_u[gwarp] = s * (1.0f / (float)D_MODEL);
}

// Kernel 2: sequential scan, one warp per batch, 8 states/lane.
// 3-step analytic lookahead: one 17-channel butterfly per 3 timesteps.
// z_{k+1} = r_k*(z_k - mu_k)*A + AB + BD*u_{k+1};  s_k = r_k*(S3_k - mu_k*Sgc) + Sbc
// z_{t+k} is affine in z_t over basis {A^k z, A^j, A^j AB, A^j BD}; all sums for
// steps t+1, t+2 close over 17 z-moment channels. z advanced exactly (3 chained affines).
__global__ void __launch_bounds__(32, 1) scan_kernel(
                            const float* __restrict__ llr,
                            const float* __restrict__ logb,
                            const float* __restrict__ cvec,
                            const float* __restrict__ logstep,
                            const float* __restrict__ lngamma,
                            const float* __restrict__ lnbeta) {
    __shared__ float su[S_LEN + 8];
    __shared__ float ss[S_LEN + 8];
    const int b = blockIdx.x;
    const int lane = threadIdx.x;

    // Stage this batch's u row into SMEM; zero the pad.
    {
        const float4* up = (const float4*)(g_u + (size_t)b * S_LEN);
        float4* sp = (float4*)su;
        #pragma unroll
        for (int k = 0; k < 16; k++) sp[lane + 32 * k] = up[lane + 32 * k];
        if (lane < 8) su[S_LEN + lane] = 0.0f;
    }
    __syncwarp();

    const float step = expf(logstep[0]);
    float A[8], AB[8], BD[8], GC[8], z[8];
    // per-lane partials for constant reductions
    float c_sgc=0,c_sbc=0;
    float c_ka1=0,c_ka2=0,c_ka3=0,c_ka4=0;
    float c_kab0=0,c_kab1=0,c_kab2=0,c_kab3=0;
    float c_kbd0=0,c_kbd1=0,c_kbd2=0,c_kbd3=0;
    float c_kab2_0=0,c_kab2_1=0,c_kab2_2=0;
    float c_kbd2_0=0,c_kbd2_1=0,c_kbd2_2=0;
    float c_kabbd0=0,c_kabbd1=0,c_kabbd2=0;
    float c_ga1=0,c_ga2=0,c_gab0=0,c_gab1=0,c_gbd0=0,c_gbd1=0;
    #pragma unroll
    for (int j = 0; j < 8; j++) {
        int i = lane + 32 * j;
        float lam = -expf(llr[i]);
        float ad  = (2.0f + step * lam) / (2.0f - step * lam);
        float bb  = expf(logb[i]);
        float bd  = step * (1.0f + ad) * bb * 0.5f;
        float g   = lngamma[i];
        float be  = lnbeta[i];
        float cc  = cvec[i];
        float a   = ad * g;
        float ab  = ad * be;
        float gc  = g * cc;
        A[j]=a; AB[j]=ab; BD[j]=bd; GC[j]=gc;
        float a2=a*a, a3=a2*a, a4=a2*a2;
        c_sgc += gc;            c_sbc += be*cc;
        c_ka1 += a;  c_ka2 += a2;  c_ka3 += a3;  c_ka4 += a4;
        c_kab0 += ab;      c_kab1 += a*ab;    c_kab2 += a2*ab;   c_kab3 += a3*ab;
        c_kbd0 += bd;      c_kbd1 += a*bd;    c_kbd2 += a2*bd;   c_kbd3 += a3*bd;
        c_kab2_0 += ab*ab; c_kab2_1 += a*ab*ab; c_kab2_2 += a2*ab*ab;
        c_kbd2_0 += bd*bd; c_kbd2_1 += a*bd*bd; c_kbd2_2 += a2*bd*bd;
        c_kabbd0 += ab*bd; c_kabbd1 += a*ab*bd; c_kabbd2 += a2*ab*bd;
        c_ga1 += gc*a;  c_ga2 += gc*a2;
        c_gab0 += gc*ab; c_gab1 += gc*a*ab;
        c_gbd0 += gc*bd; c_gbd1 += gc*a*bd;
    }
    const float Sgc=warp_sum(c_sgc),   Sbc=warp_sum(c_sbc);
    const float Ka1=warp_sum(c_ka1),   Ka2=warp_sum(c_ka2),  Ka3=warp_sum(c_ka3), Ka4=warp_sum(c_ka4);
    const float Kab0=warp_sum(c_kab0), Kab1=warp_sum(c_kab1),Kab2=warp_sum(c_kab2),Kab3=warp_sum(c_kab3);
    const float Kbd0=warp_sum(c_kbd0), Kbd1=warp_sum(c_kbd1),Kbd2=warp_sum(c_kbd2),Kbd3=warp_sum(c_kbd3);
    const float Kab2_0=warp_sum(c_kab2_0), Kab2_1=warp_sum(c_kab2_1), Kab2_2=warp_sum(c_kab2_2);
    const float Kbd2_0=warp_sum(c_kbd2_0), Kbd2_1=warp_sum(c_kbd2_1), Kbd2_2=warp_sum(c_kbd2_2);
    const float Kabbd0=warp_sum(c_kabbd0), Kabbd1=warp_sum(c_kabbd1), Kabbd2=warp_sum(c_kabbd2);
    const float Ga1=warp_sum(c_ga1),   Ga2=warp_sum(c_ga2);
    const float Gab0=warp_sum(c_gab0), Gab1=warp_sum(c_gab1);
    const float Gbd0=warp_sum(c_gbd0), Gbd1=warp_sum(c_gbd1);

    __syncwarp();
    {
        float u0 = su[0];
        #pragma unroll
        for (int j = 0; j < 8; j++) z[j] = BD[j] * u0;   // h0 = 0
    }

    const float invn = 1.0f / (float)NSTATE;
    for (int t = 0; t < S_LEN; t += 3) {
        float u1 = su[t + 1], u2 = su[t + 2], u3 = su[t + 3];

        // ── 17-channel lane-local partials over z_t ──
        float p0=0,p1=0,p2=0,p3=0,p4=0,p5=0,p6=0,p7=0,p8=0,
              p9=0,p10=0,p11=0,p12=0,p13=0,p14=0,p15=0,p16=0;
        #pragma unroll
        for (int j = 0; j < 8; j++) {
            float zz = z[j];
            float t1 = A[j]*zz, t2 = A[j]*t1, t3 = A[j]*t2, t4 = A[j]*t3;
            p0 += zz;  p1 += t1;  p2 += t2;  p3 += t3;  p4 += t4;
            p5 = fmaf(AB[j], t1, p5);  p6 = fmaf(AB[j], t2, p6);  p7 = fmaf(AB[j], t3, p7);
            p8 = fmaf(BD[j], t1, p8);  p9 = fmaf(BD[j], t2, p9);  p10 = fmaf(BD[j], t3, p10);
            p11 = fmaf(zz, zz, p11);   p12 = fmaf(t1, t1, p12);   p13 = fmaf(t2, t2, p13);
            p14 = fmaf(GC[j], zz, p14); p15 = fmaf(GC[j], t1, p15); p16 = fmaf(GC[j], t2, p16);
        }

        // ── one butterfly for all 17 channels ──
        #pragma unroll
        for (int o = 16; o; o >>= 1) {
            p0  += __shfl_xor_sync(0xffffffffu, p0,  o);
            p1  += __shfl_xor_sync(0xffffffffu, p1,  o);
            p2  += __shfl_xor_sync(0xffffffffu, p2,  o);
            p3  += __shfl_xor_sync(0xffffffffu, p3,  o);
            p4  += __shfl_xor_sync(0xffffffffu, p4,  o);
            p5  += __shfl_xor_sync(0xffffffffu, p5,  o);
            p6  += __shfl_xor_sync(0xffffffffu, p6,  o);
            p7  += __shfl_xor_sync(0xffffffffu, p7,  o);
            p8  += __shfl_xor_sync(0xffffffffu, p8,  o);
            p9  += __shfl_xor_sync(0xffffffffu, p9,  o);
            p10 += __shfl_xor_sync(0xffffffffu, p10, o);
            p11 += __shfl_xor_sync(0xffffffffu, p11, o);
            p12 += __shfl_xor_sync(0xffffffffu, p12, o);
            p13 += __shfl_xor_sync(0xffffffffu, p13, o);
            p14 += __shfl_xor_sync(0xffffffffu, p14, o);
            p15 += __shfl_xor_sync(0xffffffffu, p15, o);
            p16 += __shfl_xor_sync(0xffffffffu, p16, o);
        }

        // ── stage 0 (direct) ──
        float mu0 = p0 * invn;
        float var0 = fmaf(p11, invn, -mu0 * mu0);
        float r0 = rsqrtf(var0 + LN_EPS);
        float s0 = fmaf(r0, fmaf(-mu0, Sgc, p14), Sbc);

        // ── stage 1 (analytic): z1 = r0*A*z + g1*A + AB + u1*BD ──
        float a1 = r0;
        float g1 = -r0 * mu0;
        float S1_1 = fmaf(a1, p1, fmaf(g1, Ka1, fmaf(u1, Kbd0, Kab0)));
        float X1 = fmaf(g1, p2, fmaf(u1, p8, p5));
        float Y1;
        {
            float y = fmaf(u1 * u1, Kbd2_0, Kab2_0);
            y = fmaf(g1 * g1, Ka2, y);
            float g1_2 = g1 + g1;
            y = fmaf(g1_2, Kab1, y);
            y = fmaf(g1_2 * u1, Kbd1, y);
            Y1 = fmaf(u1 + u1, Kabbd0, y);
        }
        float S2_1 = fmaf(a1 * a1, p12, fmaf(a1 + a1, X1, Y1));
        float S3_1 = fmaf(a1, p15, fmaf(g1, Ga1, fmaf(u1, Gbd0, Gab0)));
        float mu1 = S1_1 * invn;
        float var1 = fmaf(S2_1, invn, -mu1 * mu1);
        float r1 = rsqrtf(var1 + LN_EPS);
        float s1 = fmaf(r1, fmaf(-mu1, Sgc, S3_1), Sbc);

        // ── stage 2 (analytic): z2 = a2*A^2 z + g22*A^2 + g21*A + b21*A*AB + AB + e21*A*BD + u2*BD ──
        float a2s = r1 * a1;
        float g21 = -r1 * mu1;
        float g22 = r1 * g1;
        float b21 = r1;
        float e21 = r1 * u1;
        float S1_2 = fmaf(a2s, p2,
                     fmaf(g21, Ka1, fmaf(g22, Ka2,
                     fmaf(b21, Kab1, fmaf(u2, Kbd0, fmaf(e21, Kbd1, Kab0))))));
        float X2 = fmaf(g21, p3, fmaf(g22, p4,
                   fmaf(b21, p7, fmaf(u2, p9, fmaf(e21, p10, p6)))));
        float Y2;
        {
            float y = fmaf(g21 * g21, Ka2, fmaf(g22 * g22, Ka4, (g21 + g21) * g22 * Ka3));
            y = fmaf(b21 * b21, Kab2_2, fmaf(b21 + b21, Kab2_1, y)); y += Kab2_0;
            y = fmaf(u2 * u2, Kbd2_0, fmaf(e21 * e21, Kbd2_2, fmaf((u2 + u2) * e21, Kbd2_1, y)));
            float g21_2 = g21 + g21, g22_2 = g22 + g22;
            y = fmaf(g21_2, Kab1, fmaf(g21_2 * b21, Kab2, fmaf(g22_2, Kab2, fmaf(g22_2 * b21, Kab3, y))));
            y = fmaf(g21_2 * u2, Kbd1, fmaf(g21_2 * e21, Kbd2, fmaf(g22_2 * u2, Kbd2, fmaf(g22_2 * e21, Kbd3, y))));
            float u2_2 = u2 + u2;
            y = fmaf(u2_2, Kabbd0, fmaf(e21 + e21, Kabbd1, fmaf(b21 * u2_2, Kabbd1, fmaf((b21 + b21) * e21, Kabbd2, y))));
            Y2 = y;
        }
        float S2_2 = fmaf(a2s * a2s, p13, fmaf(a2s + a2s, X2, Y2));
        float S3_2 = fmaf(a2s, p16,
                     fmaf(g21, Ga1, fmaf(g22, Ga2,
                     fmaf(b21, Gab1, fmaf(u2, Gbd0, fmaf(e21, Gbd1, Gab0))))));
        float mu2 = S1_2 * invn;
        float var2 = fmaf(S2_2, invn, -mu2 * mu2);
        float r2 = rsqrtf(var2 + LN_EPS);
        float s2 = fmaf(r2, fmaf(-mu2, Sgc, S3_2), Sbc);

        if (lane == 0) {
            ss[t] = s0; ss[t + 1] = s1; ss[t + 2] = s2;  // pads absorb overflow at t=2046
        }

        // ── advance z three steps (exact lane-local recurrence) ──
        float nrm2 = -r2 * mu2;
        #pragma unroll
        for (int j = 0; j < 8; j++) {
            float w  = fmaf(z[j], r0, g1);
            float z1 = fmaf(w, A[j], fmaf(BD[j], u1, AB[j]));
            w        = fmaf(z1, r1, g21);
            float z2 = fmaf(w, A[j], fmaf(BD[j], u2, AB[j]));
            w        = fmaf(z2, r2, nrm2);
            z[j]     = fmaf(w, A[j], fmaf(BD[j], u3, AB[j]));
        }
    }

    __syncwarp();
    {
        float4* gp = (float4*)(g_s + (size_t)b * S_LEN);
        const float4* sp = (const float4*)ss;
        #pragma unroll
        for (int k = 0; k < 16; k++) gp[lane + 32 * k] = sp[lane + 32 * k];
    }
}

// Kernel 3: out[b,s,:] = c1 * x[b,s,:] + c2 * s[b,s]   (at DRAM roofline)
__global__ void out_kernel(const float* __restrict__ x,
                           const float* __restrict__ alpha,
                           const float* __restrict__ logd,
                           float* __restrict__ out) {
    const int row = blockIdx.x;
    const int tid = threadIdx.x;
    float a_sig = 1.0f / (1.0f + expf(-alpha[0]));
    float dd = expf(logd[0]);
    float c1 = a_sig + (1.0f - a_sig) * dd;
    float c2s = (1.0f - a_sig) * g_s[row];

    const float4* xp = (const float4*)(x + (size_t)row * D_MODEL);
    float4* op = (float4*)(out + (size_t)row * D_MODEL);
    float4 v = xp[tid];
    v.x = fmaf(c1, v.x, c2s);
    v.y = fmaf(c1, v.y, c2s);
    v.z = fmaf(c1, v.z, c2s);
    v.w = fmaf(c1, v.w, c2s);
    op[tid] = v;
}

extern "C" void kernel_launch(void* const* d_in, const int* in_sizes, int n_in,
                              void* d_out, int out_size) {
    const float* x        = (const float*)d_in[0];
    const float* llr      = (const float*)d_in[1];
    const float* logb     = (const float*)d_in[2];
    const float* cvec     = (const float*)d_in[3];
    const float* logd     = (const float*)d_in[4];
    const float* logstep  = (const float*)d_in[5];
    const float* alpha    = (const float*)d_in[6];
    const float* lngamma  = (const float*)d_in[7];
    const float* lnbeta   = (const float*)d_in[8];
    float* out = (float*)d_out;

    mean_kernel<<<(B_SZ * S_LEN) / 8, 256>>>(x);
    scan_kernel<<<B_SZ, 32>>>(llr, logb, cvec, logstep, lngamma, lnbeta);
    out_kernel<<<B_SZ * S_LEN, 256>>>(x, alpha, logd, out);
}

// round 8
// speedup vs baseline: 1.0925x; 1.0925x over previous
#include <cuda_runtime.h>

#define B_SZ 32
#define S_LEN 2048
#define D_MODEL 1024
#define NSTATE 256
#define LN_EPS 1e-5f

typedef unsigned long long u64;

__device__ float g_u[B_SZ * S_LEN];
__device__ float g_s[B_SZ * S_LEN];

__device__ __forceinline__ float warp_sum(float v) {
    #pragma unroll
    for (int o = 16; o; o >>= 1) v += __shfl_xor_sync(0xffffffffu, v, o);
    return v;
}

__device__ __forceinline__ u64 pk(float lo, float hi) {
    u64 r; asm("mov.b64 %0,{%1,%2};" : "=l"(r) : "f"(lo), "f"(hi)); return r;
}
__device__ __forceinline__ void upk(u64 v, float& lo, float& hi) {
    asm("mov.b64 {%0,%1},%2;" : "=f"(lo), "=f"(hi) : "l"(v));
}
__device__ __forceinline__ u64 f2fma(u64 a, u64 b, u64 c) {
    u64 r; asm("fma.rn.f32x2 %0,%1,%2,%3;" : "=l"(r) : "l"(a), "l"(b), "l"(c)); return r;
}
__device__ __forceinline__ u64 f2mul(u64 a, u64 b) {
    u64 r; asm("mul.rn.f32x2 %0,%1,%2;" : "=l"(r) : "l"(a), "l"(b)); return r;
}
__device__ __forceinline__ u64 f2add(u64 a, u64 b) {
    u64 r; asm("add.rn.f32x2 %0,%1,%2;" : "=l"(r) : "l"(a), "l"(b)); return r;
}
__device__ __forceinline__ float upk_sum(u64 v) {
    float lo, hi; upk(v, lo, hi); return lo + hi;
}

// Kernel 1: u[b,s] = mean_k x[b,s,k].  One warp per row of 1024.  (at DRAM roofline)
__global__ void mean_kernel(const float* __restrict__ x) {
    int gwarp = (blockIdx.x * blockDim.x + threadIdx.x) >> 5;
    int lane  = threadIdx.x & 31;
    const float4* xp = (const float4*)(x + (size_t)gwarp * D_MODEL);
    float s = 0.f;
    #pragma unroll
    for (int k = 0; k < 8; k++) {
        float4 v = xp[lane + 32 * k];
        s += (v.x + v.y) + (v.z + v.w);
    }
    s = warp_sum(s);
    if (lane == 0) g_u[gwarp] = s * (1.0f / (float)D_MODEL);
}

// Kernel 2: sequential scan, one warp per batch, 8 states/lane packed as 4 f32x2.
// 2-step analytic lookahead, one 9-channel butterfly per 2 timesteps.
__global__ void __launch_bounds__(32, 1) scan_kernel(
                            const float* __restrict__ llr,
                            const float* __restrict__ logb,
                            const float* __restrict__ cvec,
                            const float* __restrict__ logstep,
                            const float* __restrict__ lngamma,
                            const float* __restrict__ lnbeta) {
    __shared__ float su[S_LEN + 4];
    __shared__ float ss[S_LEN];
    const int b = blockIdx.x;
    const int lane = threadIdx.x;
    const bool is0 = (lane == 0);

    // Stage this batch's u row into SMEM; zero pad.
    {
        const float4* up = (const float4*)(g_u + (size_t)b * S_LEN);
        float4* sp = (float4*)su;
        #pragma unroll
        for (int k = 0; k < 16; k++) sp[lane + 32 * k] = up[lane + 32 * k];
        if (lane < 4) su[S_LEN + lane] = 0.0f;
    }
    __syncwarp();

    const float step = expf(logstep[0]);
    // packed per-lane constants (pairs of states (2k, 2k+1))
    u64 Ap[4], ABp[4], BDp[4], GCp[4], QGCp[4], QABp[4], QBDp[4], Zp[4];
    float pgc=0.f, pbc=0.f, pca=0.f, pca2=0.f, pgca=0.f, pcab=0.f, pcbd=0.f,
          pgcab=0.f, pgcbd=0.f, pcaab=0.f, pcabd=0.f, pab2=0.f, pabbd=0.f, pbd2=0.f;
    float Af[8], ABf[8], BDf[8], GCf[8];
    #pragma unroll
    for (int j = 0; j < 8; j++) {
        int i = lane + 32 * j;
        float lam = -expf(llr[i]);
        float ad  = (2.0f + step * lam) / (2.0f - step * lam);
        float bb  = expf(logb[i]);
        float bd  = step * (1.0f + ad) * bb * 0.5f;
        float g   = lngamma[i];
        float be  = lnbeta[i];
        float cc  = cvec[i];
        float a   = ad * g;
        float ab  = ad * be;
        float gc  = g * cc;
        Af[j]=a; ABf[j]=ab; BDf[j]=bd; GCf[j]=gc;
        pgc  += gc;        pbc  += be*cc;
        pca  += a;         pca2 += a*a;      pgca += gc*a;
        pcab += ab;        pcbd += bd;
        pgcab+= gc*ab;     pgcbd+= gc*bd;
        pcaab+= a*ab;      pcabd+= a*bd;
        pab2 += ab*ab;     pabbd+= ab*bd;    pbd2 += bd*bd;
    }
    #pragma unroll
    for (int k = 0; k < 4; k++) {
        Ap[k]   = pk(Af[2*k],  Af[2*k+1]);
        ABp[k]  = pk(ABf[2*k], ABf[2*k+1]);
        BDp[k]  = pk(BDf[2*k], BDf[2*k+1]);
        GCp[k]  = pk(GCf[2*k], GCf[2*k+1]);
        QGCp[k] = pk(GCf[2*k]*Af[2*k],  GCf[2*k+1]*Af[2*k+1]);
        QABp[k] = pk(Af[2*k]*ABf[2*k],  Af[2*k+1]*ABf[2*k+1]);
        QBDp[k] = pk(Af[2*k]*BDf[2*k],  Af[2*k+1]*BDf[2*k+1]);
    }
    const float Sgc   = warp_sum(pgc);
    const float Sbc   = warp_sum(pbc);
    const float Ca    = warp_sum(pca);
    const float Ca2   = warp_sum(pca2);
    const float Cgca  = warp_sum(pgca);
    const float Cab   = warp_sum(pcab);
    const float Cbd   = warp_sum(pcbd);
    const float Cgcab = warp_sum(pgcab);
    const float Cgcbd = warp_sum(pgcbd);
    const float Caab  = warp_sum(pcaab);
    const float Cabd  = warp_sum(pcabd);
    const float Cab2  = warp_sum(pab2);
    const float Cabbd = warp_sum(pabbd);
    const float Cbd2  = warp_sum(pbd2);

    __syncwarp();
    {
        float u0 = su[0];
        u64 U0 = pk(u0, u0);
        #pragma unroll
        for (int k = 0; k < 4; k++) Zp[k] = f2mul(BDp[k], U0);   // h0 = 0
    }

    const float invn = 1.0f / (float)NSTATE;
    for (int t = 0; t < S_LEN; t += 2) {
        float u1 = su[t + 1], u2 = su[t + 2];   // su padded -> branchless

        // ── 9-channel packed partials over z_t ──
        u64 P0=0ull,P1=0ull,P2=0ull,P3=0ull,P4=0ull,P5=0ull,P6=0ull,P7=0ull,P8=0ull;
        #pragma unroll
        for (int k = 0; k < 4; k++) {
            u64 z  = Zp[k];
            u64 az = f2mul(Ap[k], z);
            P0 = f2add(P0, z);
            P1 = f2fma(z, z, P1);
            P2 = f2fma(GCp[k], z, P2);
            P3 = f2add(P3, az);
            P4 = f2fma(Ap[k], az, P4);
            P5 = f2fma(az, az, P5);
            P6 = f2fma(QGCp[k], z, P6);
            P7 = f2fma(QABp[k], z, P7);
            P8 = f2fma(QBDp[k], z, P8);
        }
        float p0 = upk_sum(P0), p1 = upk_sum(P1), p2 = upk_sum(P2);
        float p3 = upk_sum(P3), p4 = upk_sum(P4), p5 = upk_sum(P5);
        float p6 = upk_sum(P6), p7 = upk_sum(P7), p8 = upk_sum(P8);

        // ── one butterfly for all 9 channels (latency-capped) ──
        #pragma unroll
        for (int o = 16; o; o >>= 1) {
            p0 += __shfl_xor_sync(0xffffffffu, p0, o);
            p1 += __shfl_xor_sync(0xffffffffu, p1, o);
            p2 += __shfl_xor_sync(0xffffffffu, p2, o);
            p3 += __shfl_xor_sync(0xffffffffu, p3, o);
            p4 += __shfl_xor_sync(0xffffffffu, p4, o);
            p5 += __shfl_xor_sync(0xffffffffu, p5, o);
            p6 += __shfl_xor_sync(0xffffffffu, p6, o);
            p7 += __shfl_xor_sync(0xffffffffu, p7, o);
            p8 += __shfl_xor_sync(0xffffffffu, p8, o);
        }

        // ── step t scalars (direct) ──
        float mu  = p0 * invn;
        float var = fmaf(p1, invn, -mu * mu);
        float rs  = rsqrtf(var + LN_EPS);

        // ── step t+1 sums (analytic) — T0..T2 depend only on mu,u1 (overlap rsqrt) ──
        float T2  = fmaf(mu * mu, Ca2, fmaf(-2.0f * mu, p4, p5));
        float T1  = fmaf(u1, p8, p7) - mu * fmaf(u1, Cabd, Caab);
        float T0  = fmaf(u1 * u1, Cbd2, fmaf(2.0f * u1, Cabbd, Cab2));
        float S1n = fmaf(rs, fmaf(-mu, Ca, p3), fmaf(Cbd, u1, Cab));
        float S3n = fmaf(rs, fmaf(-mu, Cgca, p6), fmaf(Cgcbd, u1, Cgcab));
        float S2n = fmaf(rs * rs, T2, fmaf(2.0f * rs, T1, T0));

        float mun  = S1n * invn;
        float varn = fmaf(S2n, invn, -mun * mun);
        float rsn  = rsqrtf(varn + LN_EPS);

        if (is0) {
            ss[t]     = fmaf(rs,  fmaf(-mu,  Sgc, p2),  Sbc);
            ss[t + 1] = fmaf(rsn, fmaf(-mun, Sgc, S3n), Sbc);
        }

        // ── advance z two steps (exact, packed) ──
        float g1v = -rs  * mu;
        float gnv = -rsn * mun;
        u64 RS0 = pk(rs, rs),  G1 = pk(g1v, g1v);
        u64 RSN = pk(rsn, rsn), GN = pk(gnv, gnv);
        u64 U1 = pk(u1, u1), U2 = pk(u2, u2);
        #pragma unroll
        for (int k = 0; k < 4; k++) {
            u64 w   = f2fma(Zp[k], RS0, G1);          // (z - mu)*rs
            u64 c1p = f2fma(BDp[k], U1, ABp[k]);
            u64 z1  = f2fma(w, Ap[k], c1p);
            u64 w2  = f2fma(z1, RSN, GN);
            u64 c2p = f2fma(BDp[k], U2, ABp[k]);
            Zp[k]   = f2fma(w2, Ap[k], c2p);
        }
    }

    __syncwarp();
    {
        float4* gp = (float4*)(g_s + (size_t)b * S_LEN);
        const float4* sp = (const float4*)ss;
        #pragma unroll
        for (int k = 0; k < 16; k++) gp[lane + 32 * k] = sp[lane + 32 * k];
    }
}

// Kernel 3: out[b,s,:] = c1 * x[b,s,:] + c2 * s[b,s]   (at DRAM roofline)
__global__ void out_kernel(const float* __restrict__ x,
                           const float* __restrict__ alpha,
                           const float* __restrict__ logd,
                           float* __restrict__ out) {
    const int row = blockIdx.x;
    const int tid = threadIdx.x;
    float a_sig = 1.0f / (1.0f + expf(-alpha[0]));
    float dd = expf(logd[0]);
    float c1 = a_sig + (1.0f - a_sig) * dd;
    float c2s = (1.0f - a_sig) * g_s[row];

    const float4* xp = (const float4*)(x + (size_t)row * D_MODEL);
    float4* op = (float4*)(out + (size_t)row * D_MODEL);
    float4 v = xp[tid];
    v.x = fmaf(c1, v.x, c2s);
    v.y = fmaf(c1, v.y, c2s);
    v.z = fmaf(c1, v.z, c2s);
    v.w = fmaf(c1, v.w, c2s);
    op[tid] = v;
}

extern "C" void kernel_launch(void* const* d_in, const int* in_sizes, int n_in,
                              void* d_out, int out_size) {
    const float* x        = (const float*)d_in[0];
    const float* llr      = (const float*)d_in[1];
    const float* logb     = (const float*)d_in[2];
    const float* cvec     = (const float*)d_in[3];
    const float* logd     = (const float*)d_in[4];
    const float* logstep  = (const float*)d_in[5];
    const float* alpha    = (const float*)d_in[6];
    const float* lngamma  = (const float*)d_in[7];
    const float* lnbeta   = (const float*)d_in[8];
    float* out = (float*)d_out;

    mean_kernel<<<(B_SZ * S_LEN) / 8, 256>>>(x);
    scan_kernel<<<B_SZ, 32>>>(llr, logb, cvec, logstep, lngamma, lnbeta);
    out_kernel<<<B_SZ * S_LEN, 256>>>(x, alpha, logd, out);
}